// round 14
// baseline (speedup 1.0000x reference)
#include <cuda_runtime.h>
#include <cuda_fp16.h>
#include <cstdint>
#include <cstddef>

#define B_DIM   4096
#define I_DIM   256
#define O_DIM   256
#define K_BASIS (I_DIM * 64)                /* 16384 */
#define K_TOT   (K_BASIS + 2 * I_DIM)       /* 16896 */
#define N_TOT   (2 * O_DIM)                 /* 512   */

#define BM 128
#define BN 128
#define BK 128                               /* 256 bytes per k-row */
#define STAGES 3
#define NITER (K_TOT / BK)                   /* 132 */
#define NITER_BASIS (K_BASIS / BK)           /* 128 */

#define STAGE_BYTES ((BM + BN) * 256)        /* 64 KB */
#define OFF_STAGE   1024
#define SMEM_TOTAL  (OFF_STAGE + STAGES * STAGE_BYTES)   /* ~193 KB */

#define NTHREADS 384                         /* 8 consumer + 4 producer warps */

// ---------------- device scratch ----------------
__device__ __align__(128) __half g_E[(size_t)B_DIM * I_DIM * 16];  // 32 MB (eu[8],ev[8])
__device__ __align__(128) __half g_Asilu[(size_t)B_DIM * 512];     // 4 MB silu rows
__device__ __align__(128) __half g_Wt[(size_t)N_TOT * K_TOT];      // 17 MB packed W^T [n][k]
__device__ float g_bias[N_TOT];

// ---------------- PTX helpers ----------------
__device__ __forceinline__ uint32_t smem_u32(const void* p) {
    uint32_t a;
    asm("{ .reg .u64 t; cvta.to.shared.u64 t, %1; cvt.u32.u64 %0, t; }" : "=r"(a) : "l"(p));
    return a;
}
__device__ __forceinline__ uint32_t h2_bits(__half2 v) {
    union { __half2 h; uint32_t u; } c;
    c.h = v;
    return c.u;
}
__device__ __forceinline__ void cp_async16(uint32_t saddr, const void* gptr) {
    asm volatile("cp.async.cg.shared.global [%0], [%1], 16;\n" :: "r"(saddr), "l"(gptr));
}
#define CP_COMMIT() asm volatile("cp.async.commit_group;\n" ::: "memory")

#define MBAR_INIT(a, cnt) \
    asm volatile("mbarrier.init.shared.b64 [%0], %1;" :: "r"(a), "r"((uint32_t)(cnt)) : "memory")
#define MBAR_ARRIVE(a) \
    asm volatile("mbarrier.arrive.release.cta.shared.b64 _, [%0];" :: "r"(a) : "memory")
// arrive fires when all prior cp.async of this thread have completed
#define CPASYNC_MBAR_ARRIVE(a) \
    asm volatile("cp.async.mbarrier.arrive.noinc.shared.b64 [%0];" :: "r"(a) : "memory")

__device__ __forceinline__ void mbar_wait(uint32_t mbar, uint32_t parity) {
    asm volatile(
        "{\n\t.reg .pred P1;\n\t"
        "WL_%=:\n\t"
        "mbarrier.try_wait.parity.acquire.cta.shared::cta.b64 P1, [%0], %1, 0x989680;\n\t"
        "@P1 bra.uni WD_%=;\n\t"
        "bra.uni WL_%=;\n\t"
        "WD_%=:\n\t}"
        :: "r"(mbar), "r"(parity) : "memory");
}

__device__ __forceinline__ void ldsm_x4(uint32_t* r, uint32_t saddr) {
    asm volatile("ldmatrix.sync.aligned.m8n8.x4.shared.b16 {%0,%1,%2,%3}, [%4];"
                 : "=r"(r[0]), "=r"(r[1]), "=r"(r[2]), "=r"(r[3]) : "r"(saddr));
}
__device__ __forceinline__ void sts128(uint32_t saddr, uint32_t r0, uint32_t r1,
                                       uint32_t r2, uint32_t r3) {
    asm volatile("st.shared.v4.b32 [%0], {%1,%2,%3,%4};"
                 :: "r"(saddr), "r"(r0), "r"(r1), "r"(r2), "r"(r3) : "memory");
}
__device__ __forceinline__ void mma16816(float* d, const uint32_t* a, const uint32_t* b) {
    asm volatile(
        "mma.sync.aligned.m16n8k16.row.col.f32.f16.f16.f32 "
        "{%0,%1,%2,%3}, {%4,%5,%6,%7}, {%8,%9}, {%0,%1,%2,%3};\n"
        : "+f"(d[0]), "+f"(d[1]), "+f"(d[2]), "+f"(d[3])
        : "r"(a[0]), "r"(a[1]), "r"(a[2]), "r"(a[3]), "r"(b[0]), "r"(b[1]));
}

// ---------------- kernel 1: bias vector ----------------
__global__ void bias_kernel(const float* __restrict__ br, const float* __restrict__ bi) {
    int n = blockIdx.x * blockDim.x + threadIdx.x;
    if (n >= N_TOT) return;
    const float* src = (n < O_DIM) ? br : bi;
    int o = n & (O_DIM - 1);
    float s = 0.f;
    for (int i = 0; i < I_DIM; ++i) s += src[i * O_DIM + o];
    g_bias[n] = s;
}

// ---------------- kernel 2: pack W^T [n][k] fp16 ----------------
__global__ void pack_kernel(const float* __restrict__ rw, const float* __restrict__ cw,
                            const float* __restrict__ swr, const float* __restrict__ swi) {
    int gid = blockIdx.x * blockDim.x + threadIdx.x;
    int n = gid / K_TOT;
    int k = gid - n * K_TOT;
    int o = n & (O_DIM - 1);
    bool re = (n < O_DIM);
    float val;
    if (k < K_BASIS) {
        int i = k >> 6, uv = k & 63;
        const float* w = re ? rw : cw;
        val = w[((size_t)(i * O_DIM + o)) * 64 + uv];
    } else if (k < K_BASIS + I_DIM) {
        int i = k - K_BASIS;
        val = re ? swr[i * O_DIM + o] : swi[i * O_DIM + o];
    } else {
        int i = k - K_BASIS - I_DIM;
        val = re ? -swi[i * O_DIM + o] : swr[i * O_DIM + o];
    }
    g_Wt[(size_t)n * K_TOT + k] = __float2half(val);
}

// ---------------- kernel 3: E tables (eu/ev) + silu rows ----------------
__global__ void prep_kernel(const float* __restrict__ x_re, const float* __restrict__ x_im) {
    int b = blockIdx.x;
    int i = threadIdx.x;
    float xr = x_re[b * I_DIM + i];
    float xi = x_im[b * I_DIM + i];
    uint4 o0, o1;
    __half* h0 = (__half*)&o0;
    __half* h1 = (__half*)&o1;
#pragma unroll
    for (int u = 0; u < 8; ++u) {
        float lu = -2.0f + (float)u * (4.0f / 7.0f);
        float dr = xr - lu;  h0[u] = __float2half(__expf(-dr * dr));
        float di = xi - lu;  h1[u] = __float2half(__expf(-di * di));
    }
    uint4* dst = (uint4*)g_E + ((size_t)b * I_DIM + i) * 2;
    dst[0] = o0;
    dst[1] = o1;
    float sr = xr / (1.f + __expf(-xr));
    float si = xi / (1.f + __expf(-xi));
    g_Asilu[(size_t)b * 512 + i]       = __float2half(sr);
    g_Asilu[(size_t)b * 512 + 256 + i] = __float2half(si);
}

// ---------------- kernel 4: GEMM, warp-specialized, fused A generation ----------------
// warps 0-7: consumers, 64x32 warp tile (2m x 4n). warps 8-11: producers.
// k-row is 256B; swizzle within each 128B half: chunk ch of row r at
// ((ch & 7) ^ (r & 7)) * 16 + (ch >> 3) * 128
__global__ __launch_bounds__(NTHREADS, 1)
void gemm_kernel(float* __restrict__ out) {
    extern __shared__ __align__(128) char smem[];
    uint32_t sb = smem_u32(smem);

    int tid  = threadIdx.x;
    int warp = tid >> 5, lane = tid & 31;
    int bm = blockIdx.x * BM, bn = blockIdx.y * BN;

    if (tid == 0) {
#pragma unroll
        for (int s = 0; s < STAGES; ++s) {
            MBAR_INIT(sb + s * 16, 256);      // full[s]: 128 STS-release + 128 cp.async arrivals
            MBAR_INIT(sb + s * 16 + 8, 256);  // empty[s]: 256 consumer threads
        }
    }
    __syncthreads();

    if (warp >= 8) {
        // ---------------- producer ----------------
        int ptid = tid - 256;                 // 0..127; owns A row ptid
        const __half* gB = g_Wt + (size_t)bn * K_TOT;
        const uint4* eRow = (const uint4*)g_E + (size_t)(bm + ptid) * I_DIM * 2;
        int rsw = (ptid & 7);
        int s = 0, phase = 1;                 // first empty-wait passes immediately
        for (int kt = 0; kt < NITER; ++kt) {
            mbar_wait(sb + s * 16 + 8, (uint32_t)phase);
            uint32_t sA = sb + OFF_STAGE + s * STAGE_BYTES;
            uint32_t sB = sA + BM * 256;
            int k0 = kt * BK;

            if (kt < NITER_BASIS) {
                // compute A row: 2 i-values (i0=2*kt, i0+1), 64 products each
                uint32_t rowbase = sA + (uint32_t)(ptid << 8);
                const uint4* ep = eRow + (size_t)(2 * kt) * 2;
#pragma unroll
                for (int ih = 0; ih < 2; ++ih) {
                    uint4 qe = ep[2 * ih];        // eu[0..7]
                    uint4 qv = ep[2 * ih + 1];    // ev[0..7]
                    const __half* eu = (const __half*)&qe;
                    const __half2* ev2 = (const __half2*)&qv;
#pragma unroll
                    for (int u = 0; u < 8; ++u) {
                        __half2 eb = __half2half2(eu[u]);
                        __half2 r0 = __hmul2(eb, ev2[0]);
                        __half2 r1 = __hmul2(eb, ev2[1]);
                        __half2 r2 = __hmul2(eb, ev2[2]);
                        __half2 r3 = __hmul2(eb, ev2[3]);
                        int ch = ih * 8 + u;
                        uint32_t d = (uint32_t)(((ch & 7) ^ rsw) << 4)
                                   + (uint32_t)((ch >> 3) << 7);
                        sts128(rowbase + d, h2_bits(r0), h2_bits(r1),
                               h2_bits(r2), h2_bits(r3));
                    }
                }
            } else {
                // silu rows: cp.async from g_Asilu
                int k0s = k0 - K_BASIS;
#pragma unroll
                for (int j = 0; j < 16; ++j) {
                    int cc  = ptid + (j << 7);
                    int row = cc >> 4, ch = cc & 15;
                    uint32_t d = (uint32_t)(row << 8)
                               + (uint32_t)(((ch & 7) ^ (row & 7)) << 4)
                               + (uint32_t)((ch >> 3) << 7);
                    cp_async16(sA + d,
                               g_Asilu + (size_t)(bm + row) * 512 + k0s + (ch << 3));
                }
            }

            // B tile: 2048 chunks via cp.async
#pragma unroll
            for (int j = 0; j < 16; ++j) {
                int cc  = ptid + (j << 7);
                int row = cc >> 4, ch = cc & 15;
                uint32_t d = (uint32_t)(row << 8)
                           + (uint32_t)(((ch & 7) ^ (row & 7)) << 4)
                           + (uint32_t)((ch >> 3) << 7);
                cp_async16(sB + d, gB + (size_t)row * K_TOT + k0 + (ch << 3));
            }
            CP_COMMIT();
            MBAR_ARRIVE(sb + s * 16);            // release for STS (A tile)
            CPASYNC_MBAR_ARRIVE(sb + s * 16);    // completion of cp.async (B / silu A)
            if (++s == STAGES) { s = 0; phase ^= 1; }
        }
        return;
    }

    // ---------------- consumer: 64x32 warp tile ----------------
    int wm = (warp & 1) * 64;                 // 2 m-warps
    int wn = (warp >> 1) * 32;                // 4 n-warps

    int ra  = wm + (((lane >> 3) & 1) << 3) + (lane & 7);  // A row (without mi*16)
    int ca  = lane >> 4;                                   // 0/1: k16 half
    int swa = ra & 7;
    int nb  = wn + ((lane >> 4) << 3) + (lane & 7);        // B row (without nn*16)
    int cb  = (lane >> 3) & 1;
    int swb = nb & 7;

    float acc[4][4][4];
#pragma unroll
    for (int mi = 0; mi < 4; ++mi)
#pragma unroll
        for (int ni = 0; ni < 4; ++ni)
#pragma unroll
            for (int c = 0; c < 4; ++c) acc[mi][ni][c] = 0.f;

    int s = 0, phase = 0;
    for (int kt = 0; kt < NITER; ++kt) {
        mbar_wait(sb + s * 16, (uint32_t)phase);

        uint32_t baseA = sb + OFF_STAGE + s * STAGE_BYTES + (uint32_t)(ra << 8);
        uint32_t baseB = sb + OFF_STAGE + s * STAGE_BYTES + BM * 256 + (uint32_t)(nb << 8);

#pragma unroll
        for (int ks = 0; ks < 8; ++ks) {       // eight k16 steps per BK=128
            uint32_t af[4][4];
            uint32_t bf[4][2];
            int chA = 2 * ks + ca;
            int chB = 2 * ks + cb;
            uint32_t offA = (uint32_t)((((chA & 7) ^ swa) << 4) + ((chA >> 3) << 7));
            uint32_t offB = (uint32_t)((((chB & 7) ^ swb) << 4) + ((chB >> 3) << 7));
#pragma unroll
            for (int mi = 0; mi < 4; ++mi)
                ldsm_x4(af[mi], baseA + (uint32_t)(mi * 16 * 256) + offA);
#pragma unroll
            for (int nn = 0; nn < 2; ++nn) {
                uint32_t t4[4];
                ldsm_x4(t4, baseB + (uint32_t)(nn * 16 * 256) + offB);
                bf[2 * nn][0]     = t4[0];
                bf[2 * nn][1]     = t4[1];
                bf[2 * nn + 1][0] = t4[2];
                bf[2 * nn + 1][1] = t4[3];
            }
#pragma unroll
            for (int mi = 0; mi < 4; ++mi)
#pragma unroll
                for (int ni = 0; ni < 4; ++ni)
                    mma16816(acc[mi][ni], af[mi], bf[ni]);
        }
        MBAR_ARRIVE(sb + s * 16 + 8);
        if (++s == STAGES) { s = 0; phase ^= 1; }
    }

    // epilogue: out[(b*O + o)*2 + part] = acc + bias[n]
    int g = lane >> 2, t = lane & 3;
#pragma unroll
    for (int mi = 0; mi < 4; ++mi) {
#pragma unroll
        for (int ni = 0; ni < 4; ++ni) {
            int row0 = bm + wm + mi * 16 + g;
            int col0 = bn + wn + ni * 8 + 2 * t;
            float b0 = g_bias[col0];
            float b1 = g_bias[col0 + 1];
            int o0 = col0 & (O_DIM - 1);
            int part = col0 >> 8;          // whole 128-wide tile is same part
            size_t base0 = ((size_t)row0 * O_DIM + o0) * 2 + part;
            size_t base8 = ((size_t)(row0 + 8) * O_DIM + o0) * 2 + part;
            out[base0]     = acc[mi][ni][0] + b0;
            out[base0 + 2] = acc[mi][ni][1] + b1;
            out[base8]     = acc[mi][ni][2] + b0;
            out[base8 + 2] = acc[mi][ni][3] + b1;
        }
    }
}

// ---------------- launch ----------------
extern "C" void kernel_launch(void* const* d_in, const int* in_sizes, int n_in,
                              void* d_out, int out_size) {
    const float* x_re = (const float*)d_in[0];
    const float* x_im = (const float*)d_in[1];
    const float* rw   = (const float*)d_in[2];
    const float* cw   = (const float*)d_in[3];
    const float* swr  = (const float*)d_in[4];
    const float* swi  = (const float*)d_in[5];
    const float* sbr  = (const float*)d_in[6];
    const float* sbi  = (const float*)d_in[7];
    float* out = (float*)d_out;

    cudaFuncSetAttribute(gemm_kernel, cudaFuncAttributeMaxDynamicSharedMemorySize, SMEM_TOTAL);

    bias_kernel<<<2, 256>>>(sbr, sbi);
    pack_kernel<<<(N_TOT * K_TOT) / 256, 256>>>(rw, cw, swr, swi);
    prep_kernel<<<B_DIM, I_DIM>>>(x_re, x_im);

    dim3 grid(B_DIM / BM, N_TOT / BN);   // 32 x 4 = 128 CTAs
    gemm_kernel<<<grid, NTHREADS, SMEM_TOTAL>>>(out);
}

// round 15
// speedup vs baseline: 1.0808x; 1.0808x over previous
#include <cuda_runtime.h>
#include <cuda_fp16.h>
#include <cstdint>
#include <cstddef>

#define B_DIM   4096
#define I_DIM   256
#define O_DIM   256
#define K_BASIS (I_DIM * 64)                /* 16384 */
#define K_TOT   (K_BASIS + 2 * I_DIM)       /* 16896 */
#define N_TOT   (2 * O_DIM)                 /* 512   */

#define BM 128
#define BN 128
#define BK 128                               /* 256 bytes per k-row */
#define STAGES 3
#define NITER (K_TOT / BK)                   /* 132 */
#define NITER_BASIS (K_BASIS / BK)           /* 128 */

#define STAGE_BYTES ((BM + BN) * 256)        /* 64 KB */
#define OFF_STAGE   1024
#define SMEM_TOTAL  (OFF_STAGE + STAGES * STAGE_BYTES)   /* ~193 KB */

#define NTHREADS 384                         /* 8 consumer + 4 producer warps */
#define PB 16                                /* b-rows per prep block */

// ---------------- device scratch ----------------
// g_E layout: [i][b] -> entry (i*B_DIM + b) is 32B = (eu[8], ev[8]) fp16
__device__ __align__(128) __half g_E[(size_t)I_DIM * B_DIM * 16];  // 32 MB
__device__ __align__(128) __half g_Asilu[(size_t)B_DIM * 512];     // 4 MB silu rows
__device__ __align__(128) __half g_Wt[(size_t)N_TOT * K_TOT];      // 17 MB packed W^T [n][k]
__device__ float g_bias[N_TOT];

// ---------------- PTX helpers ----------------
__device__ __forceinline__ uint32_t smem_u32(const void* p) {
    uint32_t a;
    asm("{ .reg .u64 t; cvta.to.shared.u64 t, %1; cvt.u32.u64 %0, t; }" : "=r"(a) : "l"(p));
    return a;
}
__device__ __forceinline__ uint32_t h2_bits(__half2 v) {
    union { __half2 h; uint32_t u; } c;
    c.h = v;
    return c.u;
}
__device__ __forceinline__ void cp_async16(uint32_t saddr, const void* gptr) {
    asm volatile("cp.async.cg.shared.global [%0], [%1], 16;\n" :: "r"(saddr), "l"(gptr));
}
#define CP_COMMIT() asm volatile("cp.async.commit_group;\n" ::: "memory")

#define MBAR_INIT(a, cnt) \
    asm volatile("mbarrier.init.shared.b64 [%0], %1;" :: "r"(a), "r"((uint32_t)(cnt)) : "memory")
#define MBAR_ARRIVE(a) \
    asm volatile("mbarrier.arrive.release.cta.shared.b64 _, [%0];" :: "r"(a) : "memory")
#define CPASYNC_MBAR_ARRIVE(a) \
    asm volatile("cp.async.mbarrier.arrive.noinc.shared.b64 [%0];" :: "r"(a) : "memory")

__device__ __forceinline__ void mbar_wait(uint32_t mbar, uint32_t parity) {
    asm volatile(
        "{\n\t.reg .pred P1;\n\t"
        "WL_%=:\n\t"
        "mbarrier.try_wait.parity.acquire.cta.shared::cta.b64 P1, [%0], %1, 0x989680;\n\t"
        "@P1 bra.uni WD_%=;\n\t"
        "bra.uni WL_%=;\n\t"
        "WD_%=:\n\t}"
        :: "r"(mbar), "r"(parity) : "memory");
}

__device__ __forceinline__ void ldsm_x4(uint32_t* r, uint32_t saddr) {
    asm volatile("ldmatrix.sync.aligned.m8n8.x4.shared.b16 {%0,%1,%2,%3}, [%4];"
                 : "=r"(r[0]), "=r"(r[1]), "=r"(r[2]), "=r"(r[3]) : "r"(saddr));
}
__device__ __forceinline__ void sts128(uint32_t saddr, uint32_t r0, uint32_t r1,
                                       uint32_t r2, uint32_t r3) {
    asm volatile("st.shared.v4.b32 [%0], {%1,%2,%3,%4};"
                 :: "r"(saddr), "r"(r0), "r"(r1), "r"(r2), "r"(r3) : "memory");
}
__device__ __forceinline__ void mma16816(float* d, const uint32_t* a, const uint32_t* b) {
    asm volatile(
        "mma.sync.aligned.m16n8k16.row.col.f32.f16.f16.f32 "
        "{%0,%1,%2,%3}, {%4,%5,%6,%7}, {%8,%9}, {%0,%1,%2,%3};\n"
        : "+f"(d[0]), "+f"(d[1]), "+f"(d[2]), "+f"(d[3])
        : "r"(a[0]), "r"(a[1]), "r"(a[2]), "r"(a[3]), "r"(b[0]), "r"(b[1]));
}

// ---------------- kernel 1: bias vector (parallel reduce) ----------------
__global__ __launch_bounds__(256) void bias_kernel(const float* __restrict__ br,
                                                   const float* __restrict__ bi) {
    int n = blockIdx.x;                        // 512 blocks
    const float* src = (n < O_DIM) ? br : bi;
    int o = n & (O_DIM - 1);
    float s = src[threadIdx.x * O_DIM + o];
    __shared__ float red[8];
#pragma unroll
    for (int off = 16; off; off >>= 1) s += __shfl_down_sync(0xFFFFFFFFu, s, off);
    if ((threadIdx.x & 31) == 0) red[threadIdx.x >> 5] = s;
    __syncthreads();
    if (threadIdx.x == 0) {
        float t = 0.f;
#pragma unroll
        for (int w = 0; w < 8; ++w) t += red[w];
        g_bias[n] = t;
    }
}

// ---------------- kernel 2: pack W^T [n][k] fp16 ----------------
__global__ void pack_kernel(const float* __restrict__ rw, const float* __restrict__ cw,
                            const float* __restrict__ swr, const float* __restrict__ swi) {
    int gid = blockIdx.x * blockDim.x + threadIdx.x;
    int n = gid / K_TOT;
    int k = gid - n * K_TOT;
    int o = n & (O_DIM - 1);
    bool re = (n < O_DIM);
    float val;
    if (k < K_BASIS) {
        int i = k >> 6, uv = k & 63;
        const float* w = re ? rw : cw;
        val = w[((size_t)(i * O_DIM + o)) * 64 + uv];
    } else if (k < K_BASIS + I_DIM) {
        int i = k - K_BASIS;
        val = re ? swr[i * O_DIM + o] : swi[i * O_DIM + o];
    } else {
        int i = k - K_BASIS - I_DIM;
        val = re ? -swi[i * O_DIM + o] : swr[i * O_DIM + o];
    }
    g_Wt[(size_t)n * K_TOT + k] = __float2half(val);
}

// ---------------- kernel 3: E tables (transposed) + silu rows ----------------
// exp recurrence: e_{u+1} = e_u * r_u ; r_{u+1} = r_u * exp(-2h^2)
__device__ __forceinline__ void exp_row(float x, uint32_t* out /*4 u32 = 8 half*/) {
    const float h  = 0.571428571f;            /* 4/7 */
    const float c  = 0.520450294f;            /* exp(-2h^2) */
    float d0 = x + 2.0f;
    float e = __expf(-d0 * d0);
    float r = __expf(2.0f * h * d0 - 0.326530612f /* h^2 */);
    float v[8];
    v[0] = e;
#pragma unroll
    for (int u = 1; u < 8; ++u) { e = e * r; r = r * c; v[u] = e; }
#pragma unroll
    for (int u = 0; u < 8; u += 2)
        out[u >> 1] = h2_bits(__floats2half2_rn(v[u], v[u + 1]));
}

__global__ __launch_bounds__(256) void prep_kernel(const float* __restrict__ x_re,
                                                   const float* __restrict__ x_im) {
    __shared__ float sxr[PB][I_DIM];
    __shared__ float sxi[PB][I_DIM];
    int b0 = blockIdx.x * PB;
    int tid = threadIdx.x;
#pragma unroll
    for (int j = 0; j < PB; ++j) {
        sxr[j][tid] = x_re[(size_t)(b0 + j) * I_DIM + tid];
        sxi[j][tid] = x_im[(size_t)(b0 + j) * I_DIM + tid];
    }
    __syncthreads();

    int bl = tid & (PB - 1);
    int iq = tid >> 4;                         // 16 i-groups of 16
    int b = b0 + bl;
    uint32_t sre2[8], sim2[8];
    float pr = 0.f, pi = 0.f;
#pragma unroll
    for (int jj = 0; jj < 16; ++jj) {
        int i = iq * 16 + jj;
        float xr = sxr[bl][i], xi = sxi[bl][i];
        uint32_t eo[4], vo[4];
        exp_row(xr, eo);
        exp_row(xi, vo);
        uint4* dst = (uint4*)g_E + ((size_t)i * B_DIM + b) * 2;
        dst[0] = make_uint4(eo[0], eo[1], eo[2], eo[3]);
        dst[1] = make_uint4(vo[0], vo[1], vo[2], vo[3]);
        float sr = xr / (1.f + __expf(-xr));
        float si = xi / (1.f + __expf(-xi));
        if ((jj & 1) == 0) { pr = sr; pi = si; }
        else {
            sre2[jj >> 1] = h2_bits(__floats2half2_rn(pr, sr));
            sim2[jj >> 1] = h2_bits(__floats2half2_rn(pi, si));
        }
    }
    uint4* ds = (uint4*)(g_Asilu + (size_t)b * 512 + iq * 16);
    ds[0] = make_uint4(sre2[0], sre2[1], sre2[2], sre2[3]);
    ds[1] = make_uint4(sre2[4], sre2[5], sre2[6], sre2[7]);
    uint4* ds2 = (uint4*)(g_Asilu + (size_t)b * 512 + 256 + iq * 16);
    ds2[0] = make_uint4(sim2[0], sim2[1], sim2[2], sim2[3]);
    ds2[1] = make_uint4(sim2[4], sim2[5], sim2[6], sim2[7]);
}

// ---------------- kernel 4: GEMM, warp-specialized, fused A generation ----------------
__device__ __forceinline__ void gen_a_half(uint32_t rowbase, int ih, int rsw,
                                           uint4 qe, uint4 qv) {
    const __half* eu = (const __half*)&qe;
    const __half2* ev2 = (const __half2*)&qv;
#pragma unroll
    for (int u = 0; u < 8; ++u) {
        __half2 eb2 = __half2half2(eu[u]);
        __half2 r0 = __hmul2(eb2, ev2[0]);
        __half2 r1 = __hmul2(eb2, ev2[1]);
        __half2 r2 = __hmul2(eb2, ev2[2]);
        __half2 r3 = __hmul2(eb2, ev2[3]);
        int ch = ih * 8 + u;
        uint32_t d = (uint32_t)(((ch & 7) ^ rsw) << 4) + (uint32_t)((ch >> 3) << 7);
        sts128(rowbase + d, h2_bits(r0), h2_bits(r1), h2_bits(r2), h2_bits(r3));
    }
}

__global__ __launch_bounds__(NTHREADS, 1)
void gemm_kernel(float* __restrict__ out) {
    extern __shared__ __align__(128) char smem[];
    uint32_t sb = smem_u32(smem);

    int tid  = threadIdx.x;
    int warp = tid >> 5, lane = tid & 31;
    int bm = blockIdx.x * BM, bn = blockIdx.y * BN;

    if (tid == 0) {
#pragma unroll
        for (int s = 0; s < STAGES; ++s) {
            MBAR_INIT(sb + s * 16, 256);      // full: 128 STS-release + 128 cp.async arrivals
            MBAR_INIT(sb + s * 16 + 8, 256);  // empty: 256 consumer threads
        }
    }
    __syncthreads();

    if (warp >= 8) {
        // ---------------- producer ----------------
        int ptid = tid - 256;                 // 0..127; owns A row ptid
        const __half* gB = g_Wt + (size_t)bn * K_TOT;
        const uint4* eT = (const uint4*)g_E;
        const size_t eb = (size_t)(bm + ptid) * 2;   // i=0 entry; i stride = B_DIM*2 u4
        int rsw = (ptid & 7);

        // preload E for kt = 0 (i = 0, 1); coalesced: lanes consecutive
        uint4 qe0 = eT[eb],              qv0 = eT[eb + 1];
        uint4 qe1 = eT[eb + 2 * B_DIM],  qv1 = eT[eb + 2 * B_DIM + 1];

        int s = 0, phase = 1;                 // first empty-wait passes immediately
        for (int kt = 0; kt < NITER; ++kt) {
            mbar_wait(sb + s * 16 + 8, (uint32_t)phase);
            uint32_t sA = sb + OFF_STAGE + s * STAGE_BYTES;
            uint32_t sB = sA + BM * 256;
            int k0 = kt * BK;

            if (kt < NITER_BASIS) {
                uint32_t rowbase = sA + (uint32_t)(ptid << 8);
                gen_a_half(rowbase, 0, rsw, qe0, qv0);
                gen_a_half(rowbase, 1, rsw, qe1, qv1);
                if (kt + 1 < NITER_BASIS) {   // prefetch next iteration's E rows
                    size_t a = eb + (size_t)(2 * (kt + 1)) * (2 * B_DIM);
                    qe0 = eT[a];               qv0 = eT[a + 1];
                    qe1 = eT[a + 2 * B_DIM];   qv1 = eT[a + 2 * B_DIM + 1];
                }
            } else {
                // silu rows: cp.async from g_Asilu
                int k0s = k0 - K_BASIS;
#pragma unroll
                for (int j = 0; j < 16; ++j) {
                    int cc  = ptid + (j << 7);
                    int row = cc >> 4, ch = cc & 15;
                    uint32_t d = (uint32_t)(row << 8)
                               + (uint32_t)(((ch & 7) ^ (row & 7)) << 4)
                               + (uint32_t)((ch >> 3) << 7);
                    cp_async16(sA + d,
                               g_Asilu + (size_t)(bm + row) * 512 + k0s + (ch << 3));
                }
            }

            // B tile: 2048 chunks via cp.async
#pragma unroll
            for (int j = 0; j < 16; ++j) {
                int cc  = ptid + (j << 7);
                int row = cc >> 4, ch = cc & 15;
                uint32_t d = (uint32_t)(row << 8)
                           + (uint32_t)(((ch & 7) ^ (row & 7)) << 4)
                           + (uint32_t)((ch >> 3) << 7);
                cp_async16(sB + d, gB + (size_t)row * K_TOT + k0 + (ch << 3));
            }
            CP_COMMIT();
            MBAR_ARRIVE(sb + s * 16);            // release for STS (A tile)
            CPASYNC_MBAR_ARRIVE(sb + s * 16);    // completion of cp.async (B / silu A)
            if (++s == STAGES) { s = 0; phase ^= 1; }
        }
        return;
    }

    // ---------------- consumer: 64x32 warp tile ----------------
    int wm = (warp & 1) * 64;                 // 2 m-warps
    int wn = (warp >> 1) * 32;                // 4 n-warps

    int ra  = wm + (((lane >> 3) & 1) << 3) + (lane & 7);  // A row (without mi*16)
    int ca  = lane >> 4;                                   // 0/1: k16 half
    int swa = ra & 7;
    int nb  = wn + ((lane >> 4) << 3) + (lane & 7);        // B row (without nn*16)
    int cb  = (lane >> 3) & 1;
    int swb = nb & 7;

    float acc[4][4][4];
#pragma unroll
    for (int mi = 0; mi < 4; ++mi)
#pragma unroll
        for (int ni = 0; ni < 4; ++ni)
#pragma unroll
            for (int c = 0; c < 4; ++c) acc[mi][ni][c] = 0.f;

    int s = 0, phase = 0;
    for (int kt = 0; kt < NITER; ++kt) {
        mbar_wait(sb + s * 16, (uint32_t)phase);

        uint32_t baseA = sb + OFF_STAGE + s * STAGE_BYTES + (uint32_t)(ra << 8);
        uint32_t baseB = sb + OFF_STAGE + s * STAGE_BYTES + BM * 256 + (uint32_t)(nb << 8);

#pragma unroll
        for (int ks = 0; ks < 8; ++ks) {       // eight k16 steps per BK=128
            uint32_t af[4][4];
            uint32_t bf[4][2];
            int chA = 2 * ks + ca;
            int chB = 2 * ks + cb;
            uint32_t offA = (uint32_t)((((chA & 7) ^ swa) << 4) + ((chA >> 3) << 7));
            uint32_t offB = (uint32_t)((((chB & 7) ^ swb) << 4) + ((chB >> 3) << 7));
#pragma unroll
            for (int mi = 0; mi < 4; ++mi)
                ldsm_x4(af[mi], baseA + (uint32_t)(mi * 16 * 256) + offA);
#pragma unroll
            for (int nn = 0; nn < 2; ++nn) {
                uint32_t t4[4];
                ldsm_x4(t4, baseB + (uint32_t)(nn * 16 * 256) + offB);
                bf[2 * nn][0]     = t4[0];
                bf[2 * nn][1]     = t4[1];
                bf[2 * nn + 1][0] = t4[2];
                bf[2 * nn + 1][1] = t4[3];
            }
#pragma unroll
            for (int mi = 0; mi < 4; ++mi)
#pragma unroll
                for (int ni = 0; ni < 4; ++ni)
                    mma16816(acc[mi][ni], af[mi], bf[ni]);
        }
        MBAR_ARRIVE(sb + s * 16 + 8);
        if (++s == STAGES) { s = 0; phase ^= 1; }
    }

    // epilogue: out[(b*O + o)*2 + part] = acc + bias[n]
    int g = lane >> 2, t = lane & 3;
#pragma unroll
    for (int mi = 0; mi < 4; ++mi) {
#pragma unroll
        for (int ni = 0; ni < 4; ++ni) {
            int row0 = bm + wm + mi * 16 + g;
            int col0 = bn + wn + ni * 8 + 2 * t;
            float b0 = g_bias[col0];
            float b1 = g_bias[col0 + 1];
            int o0 = col0 & (O_DIM - 1);
            int part = col0 >> 8;          // whole 128-wide tile is same part
            size_t base0 = ((size_t)row0 * O_DIM + o0) * 2 + part;
            size_t base8 = ((size_t)(row0 + 8) * O_DIM + o0) * 2 + part;
            out[base0]     = acc[mi][ni][0] + b0;
            out[base0 + 2] = acc[mi][ni][1] + b1;
            out[base8]     = acc[mi][ni][2] + b0;
            out[base8 + 2] = acc[mi][ni][3] + b1;
        }
    }
}

// ---------------- launch ----------------
extern "C" void kernel_launch(void* const* d_in, const int* in_sizes, int n_in,
                              void* d_out, int out_size) {
    const float* x_re = (const float*)d_in[0];
    const float* x_im = (const float*)d_in[1];
    const float* rw   = (const float*)d_in[2];
    const float* cw   = (const float*)d_in[3];
    const float* swr  = (const float*)d_in[4];
    const float* swi  = (const float*)d_in[5];
    const float* sbr  = (const float*)d_in[6];
    const float* sbi  = (const float*)d_in[7];
    float* out = (float*)d_out;

    cudaFuncSetAttribute(gemm_kernel, cudaFuncAttributeMaxDynamicSharedMemorySize, SMEM_TOTAL);

    bias_kernel<<<N_TOT, 256>>>(sbr, sbi);
    pack_kernel<<<(N_TOT * K_TOT) / 256, 256>>>(rw, cw, swr, swi);
    prep_kernel<<<B_DIM / PB, 256>>>(x_re, x_im);

    dim3 grid(B_DIM / BM, N_TOT / BN);   // 32 x 4 = 128 CTAs
    gemm_kernel<<<grid, NTHREADS, SMEM_TOTAL>>>(out);
}

// round 16
// speedup vs baseline: 1.1309x; 1.0463x over previous
#include <cuda_runtime.h>
#include <cuda_fp16.h>
#include <cstdint>
#include <cstddef>

#define B_DIM   4096
#define I_DIM   256
#define O_DIM   256
#define K_BASIS (I_DIM * 64)                /* 16384 */
#define K_TOT   (K_BASIS + 2 * I_DIM)       /* 16896 */
#define N_TOT   (2 * O_DIM)                 /* 512   */

#define BM 128
#define BN 128
#define BK 128                               /* 256 bytes per k-row */
#define STAGES 3
#define NITER (K_TOT / BK)                   /* 132 */
#define NITER_BASIS (K_BASIS / BK)           /* 128 */

#define STAGE_BYTES ((BM + BN) * 256)        /* 64 KB */
#define OFF_STAGE   1024
#define SMEM_TOTAL  (OFF_STAGE + STAGES * STAGE_BYTES)   /* ~193 KB */

#define NTHREADS 384                         /* 8 consumer + 4 producer warps */
#define PB 16                                /* b-rows per prep block */

#define PACK_BLOCKS ((N_TOT * K_TOT) / 8 / 256)   /* 4224 */
#define PREP_BLOCKS (B_DIM / PB)                  /* 256  */
#define ALL_BLOCKS  (PACK_BLOCKS + PREP_BLOCKS + N_TOT)

// ---------------- device scratch ----------------
// g_E layout: [i][b] -> entry (i*B_DIM + b) is 32B = (eu[8], ev[8]) fp16
__device__ __align__(128) __half g_E[(size_t)I_DIM * B_DIM * 16];  // 32 MB
__device__ __align__(128) __half g_Asilu[(size_t)B_DIM * 512];     // 4 MB silu rows
__device__ __align__(128) __half g_Wt[(size_t)N_TOT * K_TOT];      // 17 MB packed W^T [n][k]
__device__ float g_bias[N_TOT];

// ---------------- PTX helpers ----------------
__device__ __forceinline__ uint32_t smem_u32(const void* p) {
    uint32_t a;
    asm("{ .reg .u64 t; cvta.to.shared.u64 t, %1; cvt.u32.u64 %0, t; }" : "=r"(a) : "l"(p));
    return a;
}
__device__ __forceinline__ uint32_t h2_bits(__half2 v) {
    union { __half2 h; uint32_t u; } c;
    c.h = v;
    return c.u;
}
__device__ __forceinline__ void cp_async16(uint32_t saddr, const void* gptr) {
    asm volatile("cp.async.cg.shared.global [%0], [%1], 16;\n" :: "r"(saddr), "l"(gptr));
}
#define CP_COMMIT() asm volatile("cp.async.commit_group;\n" ::: "memory")

#define MBAR_INIT(a, cnt) \
    asm volatile("mbarrier.init.shared.b64 [%0], %1;" :: "r"(a), "r"((uint32_t)(cnt)) : "memory")
#define MBAR_ARRIVE(a) \
    asm volatile("mbarrier.arrive.release.cta.shared.b64 _, [%0];" :: "r"(a) : "memory")
#define CPASYNC_MBAR_ARRIVE(a) \
    asm volatile("cp.async.mbarrier.arrive.noinc.shared.b64 [%0];" :: "r"(a) : "memory")

__device__ __forceinline__ void mbar_wait(uint32_t mbar, uint32_t parity) {
    asm volatile(
        "{\n\t.reg .pred P1;\n\t"
        "WL_%=:\n\t"
        "mbarrier.try_wait.parity.acquire.cta.shared::cta.b64 P1, [%0], %1, 0x989680;\n\t"
        "@P1 bra.uni WD_%=;\n\t"
        "bra.uni WL_%=;\n\t"
        "WD_%=:\n\t}"
        :: "r"(mbar), "r"(parity) : "memory");
}

__device__ __forceinline__ void ldsm_x4(uint32_t* r, uint32_t saddr) {
    asm volatile("ldmatrix.sync.aligned.m8n8.x4.shared.b16 {%0,%1,%2,%3}, [%4];"
                 : "=r"(r[0]), "=r"(r[1]), "=r"(r[2]), "=r"(r[3]) : "r"(saddr));
}
__device__ __forceinline__ void sts128(uint32_t saddr, uint32_t r0, uint32_t r1,
                                       uint32_t r2, uint32_t r3) {
    asm volatile("st.shared.v4.b32 [%0], {%1,%2,%3,%4};"
                 :: "r"(saddr), "r"(r0), "r"(r1), "r"(r2), "r"(r3) : "memory");
}
__device__ __forceinline__ void mma16816(float* d, const uint32_t* a, const uint32_t* b) {
    asm volatile(
        "mma.sync.aligned.m16n8k16.row.col.f32.f16.f16.f32 "
        "{%0,%1,%2,%3}, {%4,%5,%6,%7}, {%8,%9}, {%0,%1,%2,%3};\n"
        : "+f"(d[0]), "+f"(d[1]), "+f"(d[2]), "+f"(d[3])
        : "r"(a[0]), "r"(a[1]), "r"(a[2]), "r"(a[3]), "r"(b[0]), "r"(b[1]));
}

// exp recurrence: e_{u+1} = e_u * r_u ; r_{u+1} = r_u * exp(-2h^2)
__device__ __forceinline__ void exp_row(float x, uint32_t* out /*4 u32 = 8 half*/) {
    const float h  = 0.571428571f;            /* 4/7 */
    const float c  = 0.520450294f;            /* exp(-2h^2) */
    float d0 = x + 2.0f;
    float e = __expf(-d0 * d0);
    float r = __expf(2.0f * h * d0 - 0.326530612f /* h^2 */);
    float v[8];
    v[0] = e;
#pragma unroll
    for (int u = 1; u < 8; ++u) { e = e * r; r = r * c; v[u] = e; }
#pragma unroll
    for (int u = 0; u < 8; u += 2)
        out[u >> 1] = h2_bits(__floats2half2_rn(v[u], v[u + 1]));
}

// ---------------- merged prep kernel: pack + E/silu + bias in one launch ----------------
__global__ __launch_bounds__(256) void prep_all(
    const float* __restrict__ x_re, const float* __restrict__ x_im,
    const float* __restrict__ rw,  const float* __restrict__ cw,
    const float* __restrict__ swr, const float* __restrict__ swi,
    const float* __restrict__ sbr, const float* __restrict__ sbi)
{
    __shared__ float sxr[PB][I_DIM];
    __shared__ float sxi[PB][I_DIM];
    __shared__ float red[8];
    int blk = blockIdx.x;
    int tid = threadIdx.x;

    if (blk < PACK_BLOCKS) {
        // ---- pack W^T, 8 k-elements per thread (regions are 8-aligned) ----
        int g8 = (blk * 256 + tid) * 8;
        int n = g8 / K_TOT;
        int k = g8 - n * K_TOT;
        int o = n & (O_DIM - 1);
        bool re = (n < O_DIM);
        __half h[8];
        if (k < K_BASIS) {
            int i = k >> 6, uv = k & 63;
            const float* w = re ? rw : cw;
            const float4* src = (const float4*)(w + ((size_t)(i * O_DIM + o)) * 64 + uv);
            float4 f0 = src[0], f1 = src[1];
            h[0] = __float2half(f0.x); h[1] = __float2half(f0.y);
            h[2] = __float2half(f0.z); h[3] = __float2half(f0.w);
            h[4] = __float2half(f1.x); h[5] = __float2half(f1.y);
            h[6] = __float2half(f1.z); h[7] = __float2half(f1.w);
        } else if (k < K_BASIS + I_DIM) {
            int i = k - K_BASIS;
            const float* w = re ? swr : swi;
#pragma unroll
            for (int j = 0; j < 8; ++j) h[j] = __float2half(w[(i + j) * O_DIM + o]);
        } else {
            int i = k - K_BASIS - I_DIM;
#pragma unroll
            for (int j = 0; j < 8; ++j) {
                float v = re ? -swi[(i + j) * O_DIM + o] : swr[(i + j) * O_DIM + o];
                h[j] = __float2half(v);
            }
        }
        *(uint4*)(g_Wt + (size_t)n * K_TOT + k) = *(uint4*)h;
        return;
    }
    blk -= PACK_BLOCKS;

    if (blk < PREP_BLOCKS) {
        // ---- E tables (transposed [i][b]) + silu rows ----
        int b0 = blk * PB;
#pragma unroll
        for (int j = 0; j < PB; ++j) {
            sxr[j][tid] = x_re[(size_t)(b0 + j) * I_DIM + tid];
            sxi[j][tid] = x_im[(size_t)(b0 + j) * I_DIM + tid];
        }
        __syncthreads();

        int bl = tid & (PB - 1);
        int iq = tid >> 4;                     // 16 i-groups of 16
        int b = b0 + bl;
        uint32_t sre2[8], sim2[8];
        float pr = 0.f, pi = 0.f;
#pragma unroll
        for (int jj = 0; jj < 16; ++jj) {
            int i = iq * 16 + jj;
            float xr = sxr[bl][i], xi = sxi[bl][i];
            uint32_t eo[4], vo[4];
            exp_row(xr, eo);
            exp_row(xi, vo);
            uint4* dst = (uint4*)g_E + ((size_t)i * B_DIM + b) * 2;
            dst[0] = make_uint4(eo[0], eo[1], eo[2], eo[3]);
            dst[1] = make_uint4(vo[0], vo[1], vo[2], vo[3]);
            float sr = xr / (1.f + __expf(-xr));
            float si = xi / (1.f + __expf(-xi));
            if ((jj & 1) == 0) { pr = sr; pi = si; }
            else {
                sre2[jj >> 1] = h2_bits(__floats2half2_rn(pr, sr));
                sim2[jj >> 1] = h2_bits(__floats2half2_rn(pi, si));
            }
        }
        uint4* ds = (uint4*)(g_Asilu + (size_t)b * 512 + iq * 16);
        ds[0] = make_uint4(sre2[0], sre2[1], sre2[2], sre2[3]);
        ds[1] = make_uint4(sre2[4], sre2[5], sre2[6], sre2[7]);
        uint4* ds2 = (uint4*)(g_Asilu + (size_t)b * 512 + 256 + iq * 16);
        ds2[0] = make_uint4(sim2[0], sim2[1], sim2[2], sim2[3]);
        ds2[1] = make_uint4(sim2[4], sim2[5], sim2[6], sim2[7]);
        return;
    }
    blk -= PREP_BLOCKS;

    // ---- bias vector (one block per n) ----
    {
        int n = blk;
        const float* src = (n < O_DIM) ? sbr : sbi;
        int o = n & (O_DIM - 1);
        float s = src[tid * O_DIM + o];
#pragma unroll
        for (int off = 16; off; off >>= 1) s += __shfl_down_sync(0xFFFFFFFFu, s, off);
        if ((tid & 31) == 0) red[tid >> 5] = s;
        __syncthreads();
        if (tid == 0) {
            float t = 0.f;
#pragma unroll
            for (int w = 0; w < 8; ++w) t += red[w];
            g_bias[n] = t;
        }
    }
}

// ---------------- GEMM, warp-specialized, fused A generation ----------------
__device__ __forceinline__ void gen_a_half(uint32_t rowbase, int ih, int rsw,
                                           uint4 qe, uint4 qv) {
    const __half* eu = (const __half*)&qe;
    const __half2* ev2 = (const __half2*)&qv;
#pragma unroll
    for (int u = 0; u < 8; ++u) {
        __half2 eb2 = __half2half2(eu[u]);
        __half2 r0 = __hmul2(eb2, ev2[0]);
        __half2 r1 = __hmul2(eb2, ev2[1]);
        __half2 r2 = __hmul2(eb2, ev2[2]);
        __half2 r3 = __hmul2(eb2, ev2[3]);
        int ch = ih * 8 + u;
        uint32_t d = (uint32_t)(((ch & 7) ^ rsw) << 4) + (uint32_t)((ch >> 3) << 7);
        sts128(rowbase + d, h2_bits(r0), h2_bits(r1), h2_bits(r2), h2_bits(r3));
    }
}

__global__ __launch_bounds__(NTHREADS, 1)
void gemm_kernel(float* __restrict__ out) {
    extern __shared__ __align__(128) char smem[];
    uint32_t sb = smem_u32(smem);

    int tid  = threadIdx.x;
    int warp = tid >> 5, lane = tid & 31;
    int bm = blockIdx.x * BM, bn = blockIdx.y * BN;

    if (tid == 0) {
#pragma unroll
        for (int s = 0; s < STAGES; ++s) {
            MBAR_INIT(sb + s * 16, 256);      // full: 128 STS-release + 128 cp.async arrivals
            MBAR_INIT(sb + s * 16 + 8, 256);  // empty: 256 consumer threads
        }
    }
    __syncthreads();

    if (warp >= 8) {
        // ---------------- producer ----------------
        int ptid = tid - 256;                 // 0..127; owns A row ptid
        const __half* gB = g_Wt + (size_t)bn * K_TOT;
        const uint4* eT = (const uint4*)g_E;
        const size_t eb = (size_t)(bm + ptid) * 2;   // i=0 entry; i stride = B_DIM*2 u4
        int rsw = (ptid & 7);

        // preload E for kt = 0 (i = 0, 1); coalesced: lanes consecutive
        uint4 qe0 = eT[eb],              qv0 = eT[eb + 1];
        uint4 qe1 = eT[eb + 2 * B_DIM],  qv1 = eT[eb + 2 * B_DIM + 1];

        int s = 0, phase = 1;                 // first empty-wait passes immediately
        for (int kt = 0; kt < NITER; ++kt) {
            mbar_wait(sb + s * 16 + 8, (uint32_t)phase);
            uint32_t sA = sb + OFF_STAGE + s * STAGE_BYTES;
            uint32_t sB = sA + BM * 256;
            int k0 = kt * BK;

            if (kt < NITER_BASIS) {
                uint32_t rowbase = sA + (uint32_t)(ptid << 8);
                gen_a_half(rowbase, 0, rsw, qe0, qv0);
                gen_a_half(rowbase, 1, rsw, qe1, qv1);
                if (kt + 1 < NITER_BASIS) {   // prefetch next iteration's E rows
                    size_t a = eb + (size_t)(2 * (kt + 1)) * (2 * B_DIM);
                    qe0 = eT[a];               qv0 = eT[a + 1];
                    qe1 = eT[a + 2 * B_DIM];   qv1 = eT[a + 2 * B_DIM + 1];
                }
            } else {
                // silu rows: cp.async from g_Asilu
                int k0s = k0 - K_BASIS;
#pragma unroll
                for (int j = 0; j < 16; ++j) {
                    int cc  = ptid + (j << 7);
                    int row = cc >> 4, ch = cc & 15;
                    uint32_t d = (uint32_t)(row << 8)
                               + (uint32_t)(((ch & 7) ^ (row & 7)) << 4)
                               + (uint32_t)((ch >> 3) << 7);
                    cp_async16(sA + d,
                               g_Asilu + (size_t)(bm + row) * 512 + k0s + (ch << 3));
                }
            }

            // B tile: 2048 chunks via cp.async
#pragma unroll
            for (int j = 0; j < 16; ++j) {
                int cc  = ptid + (j << 7);
                int row = cc >> 4, ch = cc & 15;
                uint32_t d = (uint32_t)(row << 8)
                           + (uint32_t)(((ch & 7) ^ (row & 7)) << 4)
                           + (uint32_t)((ch >> 3) << 7);
                cp_async16(sB + d, gB + (size_t)row * K_TOT + k0 + (ch << 3));
            }
            CP_COMMIT();
            MBAR_ARRIVE(sb + s * 16);            // release for STS (A tile)
            CPASYNC_MBAR_ARRIVE(sb + s * 16);    // completion of cp.async (B / silu A)
            if (++s == STAGES) { s = 0; phase ^= 1; }
        }
        return;
    }

    // ---------------- consumer: 64x32 warp tile ----------------
    int wm = (warp & 1) * 64;                 // 2 m-warps
    int wn = (warp >> 1) * 32;                // 4 n-warps

    int ra  = wm + (((lane >> 3) & 1) << 3) + (lane & 7);  // A row (without mi*16)
    int ca  = lane >> 4;                                   // 0/1: k16 half
    int swa = ra & 7;
    int nb  = wn + ((lane >> 4) << 3) + (lane & 7);        // B row (without nn*16)
    int cb  = (lane >> 3) & 1;
    int swb = nb & 7;

    float acc[4][4][4];
#pragma unroll
    for (int mi = 0; mi < 4; ++mi)
#pragma unroll
        for (int ni = 0; ni < 4; ++ni)
#pragma unroll
            for (int c = 0; c < 4; ++c) acc[mi][ni][c] = 0.f;

    int s = 0, phase = 0;
    for (int kt = 0; kt < NITER; ++kt) {
        mbar_wait(sb + s * 16, (uint32_t)phase);

        uint32_t baseA = sb + OFF_STAGE + s * STAGE_BYTES + (uint32_t)(ra << 8);
        uint32_t baseB = sb + OFF_STAGE + s * STAGE_BYTES + BM * 256 + (uint32_t)(nb << 8);

#pragma unroll
        for (int ks = 0; ks < 8; ++ks) {       // eight k16 steps per BK=128
            uint32_t af[4][4];
            uint32_t bf[4][2];
            int chA = 2 * ks + ca;
            int chB = 2 * ks + cb;
            uint32_t offA = (uint32_t)((((chA & 7) ^ swa) << 4) + ((chA >> 3) << 7));
            uint32_t offB = (uint32_t)((((chB & 7) ^ swb) << 4) + ((chB >> 3) << 7));
#pragma unroll
            for (int mi = 0; mi < 4; ++mi)
                ldsm_x4(af[mi], baseA + (uint32_t)(mi * 16 * 256) + offA);
#pragma unroll
            for (int nn = 0; nn < 2; ++nn) {
                uint32_t t4[4];
                ldsm_x4(t4, baseB + (uint32_t)(nn * 16 * 256) + offB);
                bf[2 * nn][0]     = t4[0];
                bf[2 * nn][1]     = t4[1];
                bf[2 * nn + 1][0] = t4[2];
                bf[2 * nn + 1][1] = t4[3];
            }
#pragma unroll
            for (int mi = 0; mi < 4; ++mi)
#pragma unroll
                for (int ni = 0; ni < 4; ++ni)
                    mma16816(acc[mi][ni], af[mi], bf[ni]);
        }
        MBAR_ARRIVE(sb + s * 16 + 8);
        if (++s == STAGES) { s = 0; phase ^= 1; }
    }

    // epilogue: out[(b*O + o)*2 + part] = acc + bias[n]
    int g = lane >> 2, t = lane & 3;
#pragma unroll
    for (int mi = 0; mi < 4; ++mi) {
#pragma unroll
        for (int ni = 0; ni < 4; ++ni) {
            int row0 = bm + wm + mi * 16 + g;
            int col0 = bn + wn + ni * 8 + 2 * t;
            float b0 = g_bias[col0];
            float b1 = g_bias[col0 + 1];
            int o0 = col0 & (O_DIM - 1);
            int part = col0 >> 8;          // whole 128-wide tile is same part
            size_t base0 = ((size_t)row0 * O_DIM + o0) * 2 + part;
            size_t base8 = ((size_t)(row0 + 8) * O_DIM + o0) * 2 + part;
            out[base0]     = acc[mi][ni][0] + b0;
            out[base0 + 2] = acc[mi][ni][1] + b1;
            out[base8]     = acc[mi][ni][2] + b0;
            out[base8 + 2] = acc[mi][ni][3] + b1;
        }
    }
}

// ---------------- launch ----------------
extern "C" void kernel_launch(void* const* d_in, const int* in_sizes, int n_in,
                              void* d_out, int out_size) {
    const float* x_re = (const float*)d_in[0];
    const float* x_im = (const float*)d_in[1];
    const float* rw   = (const float*)d_in[2];
    const float* cw   = (const float*)d_in[3];
    const float* swr  = (const float*)d_in[4];
    const float* swi  = (const float*)d_in[5];
    const float* sbr  = (const float*)d_in[6];
    const float* sbi  = (const float*)d_in[7];
    float* out = (float*)d_out;

    cudaFuncSetAttribute(gemm_kernel, cudaFuncAttributeMaxDynamicSharedMemorySize, SMEM_TOTAL);

    prep_all<<<ALL_BLOCKS, 256>>>(x_re, x_im, rw, cw, swr, swi, sbr, sbi);

    dim3 grid(B_DIM / BM, N_TOT / BN);   // 32 x 4 = 128 CTAs
    gemm_kernel<<<grid, NTHREADS, SMEM_TOTAL>>>(out);
}